// round 1
// baseline (speedup 1.0000x reference)
#include <cuda_runtime.h>
#include <math.h>

#define B_SZ   1024
#define LATD   64
#define FCON   256
#define IN0    320     // LAT + FCON
#define HIDD   512
#define INTER  576     // LAT + HID
#define NOUT   512
#define NE     8
#define GH     64

// scratch (no allocs allowed)
__device__ float g_coeff[B_SZ * NE];
__device__ float g_out0[B_SZ * HIDD];
__device__ float g_out1[B_SZ * HIDD];

__device__ __forceinline__ float elu_f(float x) {
    return x > 0.0f ? x : expm1f(x);
}

// ---------------- gate: coeff = softmax(elu(elu(x@gw1+gb1)@gw2+gb2)@gw3+gb3) ----------------
__global__ __launch_bounds__(GH) void gate_kernel(
    const float* __restrict__ z, const float* __restrict__ c,
    const float* __restrict__ gw1, const float* __restrict__ gb1,
    const float* __restrict__ gw2, const float* __restrict__ gb2,
    const float* __restrict__ gw3, const float* __restrict__ gb3)
{
    __shared__ float x[IN0];
    __shared__ float h1[GH];
    __shared__ float h2[GH];
    __shared__ float lg[NE];

    int b = blockIdx.x;
    int t = threadIdx.x;  // 64 threads

    x[t] = z[b * LATD + t];
    #pragma unroll
    for (int i = t; i < FCON; i += GH) x[LATD + i] = c[b * FCON + i];
    __syncthreads();

    float acc = gb1[t];
    #pragma unroll 8
    for (int i = 0; i < IN0; i++) acc += x[i] * gw1[i * GH + t];
    h1[t] = elu_f(acc);
    __syncthreads();

    acc = gb2[t];
    #pragma unroll 8
    for (int i = 0; i < GH; i++) acc += h1[i] * gw2[i * GH + t];
    h2[t] = elu_f(acc);
    __syncthreads();

    if (t < NE) {
        float a = gb3[t];
        #pragma unroll 8
        for (int i = 0; i < GH; i++) a += h2[i] * gw3[i * NE + t];
        lg[t] = a;
    }
    __syncthreads();

    if (t < NE) {
        float m = lg[0];
        #pragma unroll
        for (int i = 1; i < NE; i++) m = fmaxf(m, lg[i]);
        float s = 0.0f;
        #pragma unroll
        for (int i = 0; i < NE; i++) s += expf(lg[i] - m);
        g_coeff[b * NE + t] = expf(lg[t] - m) / s;
    }
}

// ---------------- MoE layer as one big SGEMM ----------------
// out[b,o] = act( sum_{e,i} coeff[b,e]*inp[b,i]*w[e,i,o] + sum_e coeff[b,e]*bias[e,o] )
// A'[b, e*IN+i] = coeff[b,e]*inp[b,i] (built on the fly in the A loader)
// W flat [E*IN, 512] is exactly the contiguous layout of w[E, IN, 512].
template<int IN_DIM, bool ACT>
__global__ __launch_bounds__(256)
void moe_kernel(const float* __restrict__ z,
                const float* __restrict__ prev,   // width IN_DIM-LATD (c or previous out)
                const float* __restrict__ w,      // [NE*IN_DIM, NOUT]
                const float* __restrict__ bias,   // [NE, NOUT]
                float* __restrict__ out)          // [B, NOUT]
{
    constexpr int BM = 64, BN = 64, BK = 16, TM = 4, TN = 4;
    constexpr int PREV_W = IN_DIM - LATD;
    constexpr int KTOT = NE * IN_DIM;
    static_assert(IN_DIM % BK == 0, "K-tile must not span an expert boundary");

    __shared__ float As[BK][BM + 4];   // +4 pad: conflict-light stores, 16B-aligned rows
    __shared__ float Bs[BK][BN];

    int tid = threadIdx.x;
    int tx = tid & 15;
    int ty = tid >> 4;
    int m0 = blockIdx.y * BM;
    int n0 = blockIdx.x * BN;

    // A loader: 16 k-positions x 16 m-rows per pass, 4 passes
    int a_k  = tid & (BK - 1);
    int a_m0 = tid >> 4;       // 0..15
    // B loader: 64 n-cols x 4 k-rows per pass, 4 passes
    int b_n  = tid & (BN - 1);
    int b_k0 = tid >> 6;       // 0..3

    float acc[TM][TN] = {};

    for (int k0 = 0; k0 < KTOT; k0 += BK) {
        int e  = k0 / IN_DIM;
        int i0 = k0 - e * IN_DIM;

        // load + scale A tile
        #pragma unroll
        for (int r = 0; r < 4; r++) {
            int m   = a_m0 + r * 16;
            int row = m0 + m;
            int i   = i0 + a_k;
            float v = (i < LATD) ? z[row * LATD + i]
                                 : prev[row * PREV_W + (i - LATD)];
            As[a_k][m] = v * g_coeff[row * NE + e];
        }
        // load B tile (coalesced rows of W)
        #pragma unroll
        for (int r = 0; r < 4; r++) {
            int k = b_k0 + r * 4;
            Bs[k][b_n] = w[(size_t)(k0 + k) * NOUT + n0 + b_n];
        }
        __syncthreads();

        #pragma unroll
        for (int kk = 0; kk < BK; kk++) {
            float a[TM], bb[TN];
            #pragma unroll
            for (int i = 0; i < TM; i++) a[i] = As[kk][ty * TM + i];
            #pragma unroll
            for (int j = 0; j < TN; j++) bb[j] = Bs[kk][tx * TN + j];
            #pragma unroll
            for (int i = 0; i < TM; i++)
                #pragma unroll
                for (int j = 0; j < TN; j++)
                    acc[i][j] += a[i] * bb[j];
        }
        __syncthreads();
    }

    // epilogue: mixed bias + activation
    #pragma unroll
    for (int i = 0; i < TM; i++) {
        int row = m0 + ty * TM + i;
        float cf[NE];
        #pragma unroll
        for (int e = 0; e < NE; e++) cf[e] = g_coeff[row * NE + e];
        #pragma unroll
        for (int j = 0; j < TN; j++) {
            int col = n0 + tx * TN + j;
            float v = acc[i][j];
            #pragma unroll
            for (int e = 0; e < NE; e++) v += cf[e] * bias[e * NOUT + col];
            out[row * NOUT + col] = ACT ? elu_f(v) : v;
        }
    }
}

extern "C" void kernel_launch(void* const* d_in, const int* in_sizes, int n_in,
                              void* d_out, int out_size)
{
    const float* z   = (const float*)d_in[0];
    const float* c   = (const float*)d_in[1];
    const float* w0  = (const float*)d_in[2];
    const float* b0  = (const float*)d_in[3];
    const float* w1  = (const float*)d_in[4];
    const float* b1  = (const float*)d_in[5];
    const float* w2  = (const float*)d_in[6];
    const float* b2  = (const float*)d_in[7];
    const float* gw1 = (const float*)d_in[8];
    const float* gb1 = (const float*)d_in[9];
    const float* gw2 = (const float*)d_in[10];
    const float* gb2 = (const float*)d_in[11];
    const float* gw3 = (const float*)d_in[12];
    const float* gb3 = (const float*)d_in[13];
    float* out = (float*)d_out;

    float* out0;
    float* out1;
    cudaGetSymbolAddress((void**)&out0, g_out0);
    cudaGetSymbolAddress((void**)&out1, g_out1);

    gate_kernel<<<B_SZ, GH>>>(z, c, gw1, gb1, gw2, gb2, gw3, gb3);

    dim3 grid(NOUT / 64, B_SZ / 64);  // (8, 16) = 128 blocks
    moe_kernel<IN0,   true ><<<grid, 256>>>(z, c,    w0, b0, out0);
    moe_kernel<INTER, true ><<<grid, 256>>>(z, out0, w1, b1, out1);
    moe_kernel<INTER, false><<<grid, 256>>>(z, out1, w2, b2, out);
}